// round 1
// baseline (speedup 1.0000x reference)
#include <cuda_runtime.h>
#include <cuda_bf16.h>
#include <cstdint>

// Problem constants
#define N_ROWS 131072
#define DDIM   1024
#define KCENT  256

#define M_TILE 64
#define AS 136   // bf16 smem row stride (128 + 8 pad) for A and B tiles
#define ES 264   // fp32 smem row stride (256 + 8 pad) for epilogue

// Normalized centroids, bf16, [K][D]  (512 KB device scratch)
__device__ __nv_bfloat16 g_cn[KCENT * DDIM];

// ---------------------------------------------------------------------------
// Prepass: normalize centroids (fp32) -> bf16 scratch. 256 blocks x 256 thr.
// ---------------------------------------------------------------------------
__global__ void centroid_prep_kernel(const float* __restrict__ cent) {
    int b = blockIdx.x;           // centroid row
    int t = threadIdx.x;          // 0..255, 4 floats each
    const float4 v = reinterpret_cast<const float4*>(cent + (size_t)b * DDIM)[t];
    float s = v.x * v.x + v.y * v.y + v.z * v.z + v.w * v.w;
    #pragma unroll
    for (int o = 16; o; o >>= 1) s += __shfl_xor_sync(0xFFFFFFFFu, s, o);
    __shared__ float ws[8];
    __shared__ float s_inv;
    if ((t & 31) == 0) ws[t >> 5] = s;
    __syncthreads();
    if (t == 0) {
        float tot = 0.f;
        #pragma unroll
        for (int i = 0; i < 8; i++) tot += ws[i];
        s_inv = 1.0f / fmaxf(sqrtf(tot), 1e-8f);
    }
    __syncthreads();
    float iv = s_inv;
    __nv_bfloat16* dst = g_cn + (size_t)b * DDIM + t * 4;
    dst[0] = __float2bfloat16(v.x * iv);
    dst[1] = __float2bfloat16(v.y * iv);
    dst[2] = __float2bfloat16(v.z * iv);
    dst[3] = __float2bfloat16(v.w * iv);
}

// ---------------------------------------------------------------------------
// PTX helpers
// ---------------------------------------------------------------------------
__device__ __forceinline__ unsigned smem_u32(const void* p) {
    return (unsigned)__cvta_generic_to_shared(p);
}

__device__ __forceinline__ void ldmatrix_x4(unsigned r[4], unsigned addr) {
    asm volatile("ldmatrix.sync.aligned.m8n8.x4.shared.b16 {%0,%1,%2,%3}, [%4];"
                 : "=r"(r[0]), "=r"(r[1]), "=r"(r[2]), "=r"(r[3]) : "r"(addr));
}

__device__ __forceinline__ void mma_16816(float d[4], const unsigned a[4],
                                          unsigned b0, unsigned b1) {
    asm volatile(
        "mma.sync.aligned.m16n8k16.row.col.f32.bf16.bf16.f32 "
        "{%0,%1,%2,%3}, {%4,%5,%6,%7}, {%8,%9}, {%0,%1,%2,%3};"
        : "+f"(d[0]), "+f"(d[1]), "+f"(d[2]), "+f"(d[3])
        : "r"(a[0]), "r"(a[1]), "r"(a[2]), "r"(a[3]), "r"(b0), "r"(b1));
}

// ---------------------------------------------------------------------------
// Main fused kernel: 64-row tile x 256 centroids, 8 D-chunks of 128.
// SMEM: A [64][136] bf16 (17408 B) | B [256][136] bf16 (69632 B) | inv[64] f32
// Epilogue reuses A+B region as fp32 [64][264].
// ---------------------------------------------------------------------------
#define SMEM_A_OFF  0
#define SMEM_B_OFF  17408
#define SMEM_INV_OFF 87040
#define SMEM_TOTAL  (87040 + 256)

__global__ void __launch_bounds__(256, 2)
cluster_softmax_kernel(const float* __restrict__ batch, float* __restrict__ out) {
    extern __shared__ char smem[];
    __nv_bfloat16* sA  = reinterpret_cast<__nv_bfloat16*>(smem + SMEM_A_OFF);
    __nv_bfloat16* sB  = reinterpret_cast<__nv_bfloat16*>(smem + SMEM_B_OFF);
    float*         sInv = reinterpret_cast<float*>(smem + SMEM_INV_OFF);
    float*         sE  = reinterpret_cast<float*>(smem);   // epilogue reuse

    const int m0   = blockIdx.x * M_TILE;
    const int tid  = threadIdx.x;
    const int lane = tid & 31;
    const int w    = tid >> 5;          // warp 0..7
    const int rowGroup = w & 3;         // 16-row group for MMA
    const int colGroup = w >> 2;        // 128-col group for MMA

    float psq[8];
    #pragma unroll
    for (int j = 0; j < 8; j++) psq[j] = 0.f;

    float acc[16][4];
    #pragma unroll
    for (int t = 0; t < 16; t++)
        #pragma unroll
        for (int c = 0; c < 4; c++) acc[t][c] = 0.f;

    // precompute ldmatrix base lane offsets
    const int aRow = rowGroup * 16 + (lane & 15);
    const int aKof = (lane >> 4) << 3;
    const int bRowOf = (lane & 7) + ((lane >> 4) << 3);
    const int bKof = ((lane >> 3) & 1) << 3;

    for (int ch = 0; ch < 8; ch++) {
        const int d0 = ch * 128;
        __syncthreads();   // previous iteration's MMA reads done

        // --- load A chunk: warp w owns rows w*8 .. w*8+7; lane -> 4 floats ---
        #pragma unroll
        for (int j = 0; j < 8; j++) {
            int r = w * 8 + j;
            float4 v = *reinterpret_cast<const float4*>(
                batch + (size_t)(m0 + r) * DDIM + d0 + lane * 4);
            psq[j] += v.x * v.x + v.y * v.y + v.z * v.z + v.w * v.w;
            __nv_bfloat162* dst =
                reinterpret_cast<__nv_bfloat162*>(sA + r * AS + lane * 4);
            dst[0] = __floats2bfloat162_rn(v.x, v.y);
            dst[1] = __floats2bfloat162_rn(v.z, v.w);
        }

        // --- load B chunk: thread tid copies centroid tid's 128 bf16 (256 B) ---
        {
            const uint4* src = reinterpret_cast<const uint4*>(
                g_cn + (size_t)tid * DDIM + d0);
            uint4* dst = reinterpret_cast<uint4*>(sB + tid * AS);
            #pragma unroll
            for (int i = 0; i < 16; i++) dst[i] = src[i];
        }
        __syncthreads();

        // --- MMA over 8 k16 steps ---
        #pragma unroll
        for (int kk = 0; kk < 8; kk++) {
            const int k0 = kk * 16;
            unsigned a[4];
            ldmatrix_x4(a, smem_u32(sA + aRow * AS + k0 + aKof));
            #pragma unroll
            for (int nt = 0; nt < 8; nt++) {
                const int n0 = colGroup * 128 + nt * 16;
                unsigned b[4];
                ldmatrix_x4(b, smem_u32(sB + (n0 + bRowOf) * AS + k0 + bKof));
                mma_16816(acc[2 * nt + 0], a, b[0], b[1]);
                mma_16816(acc[2 * nt + 1], a, b[2], b[3]);
            }
        }
    }

    // --- row norms: reduce the 4..(32) lane partials per row ---
    #pragma unroll
    for (int j = 0; j < 8; j++) {
        float s = psq[j];
        #pragma unroll
        for (int o = 16; o; o >>= 1) s += __shfl_xor_sync(0xFFFFFFFFu, s, o);
        if (lane == 0) sInv[w * 8 + j] = 1.0f / fmaxf(sqrtf(s), 1e-8f);
    }
    __syncthreads();   // norms visible; MMA smem reads done -> safe to overwrite

    // --- epilogue part 1: scale, exp, scatter to sE ---
    {
        const int rbase = rowGroup * 16 + (lane >> 2);
        #pragma unroll
        for (int t = 0; t < 16; t++) {
            const int colb = colGroup * 128 + t * 8 + (lane & 3) * 2;
            #pragma unroll
            for (int c = 0; c < 4; c++) {
                const int row = rbase + ((c >> 1) << 3);
                const int col = colb + (c & 1);
                sE[row * ES + col] = __expf(acc[t][c] * sInv[row]);
            }
        }
    }
    __syncthreads();

    // --- epilogue part 2: row sums + normalized write (coalesced) ---
    #pragma unroll
    for (int j = 0; j < 8; j++) {
        const int row = w * 8 + j;
        float v[8], s = 0.f;
        #pragma unroll
        for (int i = 0; i < 8; i++) {
            v[i] = sE[row * ES + lane + i * 32];
            s += v[i];
        }
        #pragma unroll
        for (int o = 16; o; o >>= 1) s += __shfl_xor_sync(0xFFFFFFFFu, s, o);
        const float is = 1.0f / s;
        float* op = out + (size_t)(m0 + row) * KCENT;
        #pragma unroll
        for (int i = 0; i < 8; i++) op[lane + i * 32] = v[i] * is;
    }
}

// ---------------------------------------------------------------------------
extern "C" void kernel_launch(void* const* d_in, const int* in_sizes, int n_in,
                              void* d_out, int out_size) {
    const float* batch     = (const float*)d_in[0];   // [N, D] fp32
    const float* centroids = (const float*)d_in[1];   // [K, D] fp32
    float* out = (float*)d_out;                       // [N, K] fp32

    centroid_prep_kernel<<<KCENT, 256>>>(centroids);

    cudaFuncSetAttribute(cluster_softmax_kernel,
                         cudaFuncAttributeMaxDynamicSharedMemorySize, SMEM_TOTAL);
    cluster_softmax_kernel<<<N_ROWS / M_TILE, 256, SMEM_TOTAL>>>(batch, out);
}

// round 3
// speedup vs baseline: 1.6937x; 1.6937x over previous
#include <cuda_runtime.h>
#include <cuda_bf16.h>
#include <cstdint>

// Problem constants
#define N_ROWS 131072
#define DDIM   1024
#define KCENT  256
#define M_TILE 128
#define KCHUNK 64                    // bf16 elems per D-chunk
#define NCHUNKS (DDIM / KCHUNK)      // 16

#define ROWB 144                     // bytes per smem row (128 data + 16 pad)
#define A_BYTES (M_TILE * ROWB)      // 18432
#define B_BYTES (KCENT * ROWB)       // 36864
#define STAGE   (A_BYTES + B_BYTES)  // 55296
#define SM_NORM (2 * STAGE)          // float[128]
#define SM_PART (SM_NORM + 512)      // float[4*128]
#define SM_INV  (SM_PART + 2048)     // float[128]
#define SMEM_TOTAL (SM_INV + 512)

// Normalized centroids, bf16, [K][D] (512 KB device scratch)
__device__ __align__(16) __nv_bfloat16 g_cn[KCENT * DDIM];

// ---------------------------------------------------------------------------
// PTX helpers
// ---------------------------------------------------------------------------
__device__ __forceinline__ unsigned smem_u32(const void* p) {
    return (unsigned)__cvta_generic_to_shared(p);
}
__device__ __forceinline__ void ldmatrix_x4(unsigned r[4], unsigned addr) {
    asm volatile("ldmatrix.sync.aligned.m8n8.x4.shared.b16 {%0,%1,%2,%3}, [%4];"
                 : "=r"(r[0]), "=r"(r[1]), "=r"(r[2]), "=r"(r[3]) : "r"(addr));
}
__device__ __forceinline__ void mma_16816(float d[4], const unsigned a[4],
                                          unsigned b0, unsigned b1) {
    asm volatile(
        "mma.sync.aligned.m16n8k16.row.col.f32.bf16.bf16.f32 "
        "{%0,%1,%2,%3}, {%4,%5,%6,%7}, {%8,%9}, {%0,%1,%2,%3};"
        : "+f"(d[0]), "+f"(d[1]), "+f"(d[2]), "+f"(d[3])
        : "r"(a[0]), "r"(a[1]), "r"(a[2]), "r"(a[3]), "r"(b0), "r"(b1));
}
__device__ __forceinline__ void cp_async16(unsigned saddr, const void* gaddr) {
    asm volatile("cp.async.cg.shared.global [%0], [%1], 16;"
                 :: "r"(saddr), "l"(gaddr) : "memory");
}
__device__ __forceinline__ void cp_commit() {
    asm volatile("cp.async.commit_group;" ::: "memory");
}
__device__ __forceinline__ void cp_wait0() {
    asm volatile("cp.async.wait_group 0;" ::: "memory");
}
__device__ __forceinline__ void sts128(unsigned addr, uint4 v) {
    asm volatile("st.shared.v4.b32 [%0], {%1, %2, %3, %4};"
                 :: "r"(addr), "r"(v.x), "r"(v.y), "r"(v.z), "r"(v.w) : "memory");
}

// ---------------------------------------------------------------------------
// Prepass: normalize centroids (fp32) -> bf16 scratch. 256 blocks x 256 thr.
// ---------------------------------------------------------------------------
__global__ void centroid_prep_kernel(const float* __restrict__ cent) {
    int b = blockIdx.x;
    int t = threadIdx.x;
    const float4 v = reinterpret_cast<const float4*>(cent + (size_t)b * DDIM)[t];
    float s = v.x * v.x + v.y * v.y + v.z * v.z + v.w * v.w;
    #pragma unroll
    for (int o = 16; o; o >>= 1) s += __shfl_xor_sync(0xFFFFFFFFu, s, o);
    __shared__ float ws[8];
    __shared__ float s_inv;
    if ((t & 31) == 0) ws[t >> 5] = s;
    __syncthreads();
    if (t == 0) {
        float tot = 0.f;
        #pragma unroll
        for (int i = 0; i < 8; i++) tot += ws[i];
        s_inv = 1.0f / fmaxf(sqrtf(tot), 1e-8f);
    }
    __syncthreads();
    float iv = s_inv;
    __nv_bfloat16* dst = g_cn + (size_t)b * DDIM + t * 4;
    dst[0] = __float2bfloat16(v.x * iv);
    dst[1] = __float2bfloat16(v.y * iv);
    dst[2] = __float2bfloat16(v.z * iv);
    dst[3] = __float2bfloat16(v.w * iv);
}

// ---------------------------------------------------------------------------
// Main kernel: 128x256 CTA tile, 8 warps (2x4), warp tile 64x64,
// double-buffered cp.async(B) + LDG/convert(A), fused softmax epilogue.
// ---------------------------------------------------------------------------
__global__ void __launch_bounds__(256)
cluster_hmma_kernel(const float* __restrict__ batch, float* __restrict__ out) {
    extern __shared__ char smem[];
    const unsigned sb = smem_u32(smem);
    const int tid  = threadIdx.x;
    const int lane = tid & 31;
    const int w    = tid >> 5;
    const int m0   = blockIdx.x * M_TILE;

    const int rowGroup = (w & 1) * 64;    // 0 or 64
    const int colGroup = (w >> 1) * 64;   // 0,64,128,192

    // A producer mapping: 2 threads per row, 32 floats each
    const int arow  = tid >> 1;
    const int ahalf = tid & 1;
    const float* aptr = batch + (size_t)(m0 + arow) * DDIM + ahalf * 32;
    // B producer mapping: thread covers row (t>>3)+i*32, 16B chunk (t&7)
    const int brow0 = tid >> 3;
    const int bcol  = tid & 7;

    float psq = 0.f;
    float acc[4][8][4];
    #pragma unroll
    for (int mt = 0; mt < 4; mt++)
        #pragma unroll
        for (int nt = 0; nt < 8; nt++)
            #pragma unroll
            for (int c = 0; c < 4; c++) acc[mt][nt][c] = 0.f;

    // ---- helpers as lambdas ----
    auto loadA = [&](int ch, float4 v[8]) {
        const float4* p = reinterpret_cast<const float4*>(aptr + ch * KCHUNK);
        #pragma unroll
        for (int i = 0; i < 8; i++) v[i] = p[i];
    };
    auto storeA = [&](unsigned base, float4 v[8]) {
        #pragma unroll
        for (int i = 0; i < 8; i++)
            psq += v[i].x * v[i].x + v[i].y * v[i].y +
                   v[i].z * v[i].z + v[i].w * v[i].w;
        #pragma unroll
        for (int j = 0; j < 4; j++) {
            __nv_bfloat162 p0 = __floats2bfloat162_rn(v[2*j].x,   v[2*j].y);
            __nv_bfloat162 p1 = __floats2bfloat162_rn(v[2*j].z,   v[2*j].w);
            __nv_bfloat162 p2 = __floats2bfloat162_rn(v[2*j+1].x, v[2*j+1].y);
            __nv_bfloat162 p3 = __floats2bfloat162_rn(v[2*j+1].z, v[2*j+1].w);
            uint4 pk;
            pk.x = *reinterpret_cast<unsigned*>(&p0);
            pk.y = *reinterpret_cast<unsigned*>(&p1);
            pk.z = *reinterpret_cast<unsigned*>(&p2);
            pk.w = *reinterpret_cast<unsigned*>(&p3);
            sts128(base + (unsigned)(arow * ROWB + ahalf * 64 + j * 16), pk);
        }
    };
    auto loadB = [&](int ch, unsigned base) {
        #pragma unroll
        for (int i = 0; i < 8; i++) {
            int r = brow0 + i * 32;
            cp_async16(base + (unsigned)(r * ROWB + bcol * 16),
                       g_cn + (size_t)r * DDIM + ch * KCHUNK + bcol * 8);
        }
    };

    // ldmatrix lane offsets
    const unsigned aLaneOff = (unsigned)((lane & 15) * ROWB + (lane >> 4) * 16);
    const unsigned bLaneOff =
        (unsigned)(((lane & 7) + ((lane >> 4) << 3)) * ROWB + ((lane >> 3) & 1) * 16);

    // ---- prologue: stage 0 ----
    {
        float4 v[8];
        loadA(0, v);
        loadB(0, sb + A_BYTES);
        cp_commit();
        storeA(sb, v);
        cp_wait0();
    }
    __syncthreads();

    float4 av[8];

    #pragma unroll 1
    for (int ch = 0; ch < NCHUNKS; ch++) {
        const unsigned cur = sb + (unsigned)((ch & 1) * STAGE);
        const unsigned nxt = sb + (unsigned)(((ch + 1) & 1) * STAGE);

        if (ch < NCHUNKS - 1) {
            loadA(ch + 1, av);               // LDG in flight during compute
            loadB(ch + 1, nxt + A_BYTES);
            cp_commit();
        }

        // ---- compute current stage ----
        const unsigned aBase = cur + (unsigned)(rowGroup * ROWB) + aLaneOff;
        const unsigned bBase = cur + A_BYTES + (unsigned)(colGroup * ROWB) + bLaneOff;
        #pragma unroll
        for (int kk = 0; kk < 4; kk++) {
            unsigned af[4][4];
            #pragma unroll
            for (int mt = 0; mt < 4; mt++)
                ldmatrix_x4(af[mt], aBase + (unsigned)(mt * 16 * ROWB + kk * 32));
            #pragma unroll
            for (int nt2 = 0; nt2 < 4; nt2++) {
                unsigned bf[4];
                ldmatrix_x4(bf, bBase + (unsigned)(nt2 * 16 * ROWB + kk * 32));
                #pragma unroll
                for (int mt = 0; mt < 4; mt++) {
                    mma_16816(acc[mt][2*nt2],     af[mt], bf[0], bf[1]);
                    mma_16816(acc[mt][2*nt2 + 1], af[mt], bf[2], bf[3]);
                }
            }
        }

        if (ch < NCHUNKS - 1) {
            storeA(nxt, av);
            cp_wait0();
        }
        __syncthreads();
    }

    // ---- row norms ----
    {
        float tot = psq + __shfl_xor_sync(0xFFFFFFFFu, psq, 1);
        if (!ahalf)
            reinterpret_cast<float*>(smem + SM_NORM)[arow] =
                1.0f / fmaxf(sqrtf(tot), 1e-8f);
    }
    __syncthreads();

    const float* smN = reinterpret_cast<const float*>(smem + SM_NORM);
    float* smP = reinterpret_cast<float*>(smem + SM_PART);
    float* smI = reinterpret_cast<float*>(smem + SM_INV);

    // ---- exp in place + row partial sums ----
    float rsum[4][2];
    #pragma unroll
    for (int mt = 0; mt < 4; mt++) {
        const int r0 = rowGroup + mt * 16 + (lane >> 2);
        const float in0 = smN[r0], in1 = smN[r0 + 8];
        float s0 = 0.f, s1 = 0.f;
        #pragma unroll
        for (int nt = 0; nt < 8; nt++) {
            float e0 = __expf(acc[mt][nt][0] * in0);
            float e1 = __expf(acc[mt][nt][1] * in0);
            float e2 = __expf(acc[mt][nt][2] * in1);
            float e3 = __expf(acc[mt][nt][3] * in1);
            acc[mt][nt][0] = e0; acc[mt][nt][1] = e1;
            acc[mt][nt][2] = e2; acc[mt][nt][3] = e3;
            s0 += e0 + e1;
            s1 += e2 + e3;
        }
        rsum[mt][0] = s0;
        rsum[mt][1] = s1;
    }
    #pragma unroll
    for (int mt = 0; mt < 4; mt++)
        #pragma unroll
        for (int rh = 0; rh < 2; rh++) {
            float s = rsum[mt][rh];
            s += __shfl_xor_sync(0xFFFFFFFFu, s, 1);
            s += __shfl_xor_sync(0xFFFFFFFFu, s, 2);
            rsum[mt][rh] = s;
        }
    if ((lane & 3) == 0) {
        const int cg = (w >> 1) * 128;
        #pragma unroll
        for (int mt = 0; mt < 4; mt++)
            #pragma unroll
            for (int rh = 0; rh < 2; rh++)
                smP[cg + rowGroup + mt * 16 + (lane >> 2) + 8 * rh] = rsum[mt][rh];
    }
    __syncthreads();
    if (tid < 128)
        smI[tid] = 1.0f / (smP[tid] + smP[128 + tid] + smP[256 + tid] + smP[384 + tid]);
    __syncthreads();

    // ---- scaled stores ----
    #pragma unroll
    for (int mt = 0; mt < 4; mt++) {
        const int r0 = rowGroup + mt * 16 + (lane >> 2);
        const float is0 = smI[r0], is1 = smI[r0 + 8];
        float* o0 = out + (size_t)(m0 + r0) * KCENT + colGroup + (lane & 3) * 2;
        float* o1 = o0 + (size_t)8 * KCENT;
        #pragma unroll
        for (int nt = 0; nt < 8; nt++) {
            float2 v0 = make_float2(acc[mt][nt][0] * is0, acc[mt][nt][1] * is0);
            float2 v1 = make_float2(acc[mt][nt][2] * is1, acc[mt][nt][3] * is1);
            *reinterpret_cast<float2*>(o0 + nt * 8) = v0;
            *reinterpret_cast<float2*>(o1 + nt * 8) = v1;
        }
    }
}

// ---------------------------------------------------------------------------
extern "C" void kernel_launch(void* const* d_in, const int* in_sizes, int n_in,
                              void* d_out, int out_size) {
    const float* batch     = (const float*)d_in[0];   // [N, D] fp32
    const float* centroids = (const float*)d_in[1];   // [K, D] fp32
    float* out = (float*)d_out;                       // [N, K] fp32

    centroid_prep_kernel<<<KCENT, 256>>>(centroids);

    cudaFuncSetAttribute(cluster_hmma_kernel,
                         cudaFuncAttributeMaxDynamicSharedMemorySize, SMEM_TOTAL);
    cluster_hmma_kernel<<<N_ROWS / M_TILE, 256, SMEM_TOTAL>>>(batch, out);
}